// round 3
// baseline (speedup 1.0000x reference)
#include <cuda_runtime.h>
#include <cstdint>

#define N_NODES 50000
#define D 128
#define N_EDGES 625000

// Scratch (no cudaMalloc allowed)
__device__ float g_mean[(size_t)N_NODES * D];   // 25.6 MB
__device__ int   g_cnt[N_NODES];                // degree
__device__ int   g_start[N_NODES];              // CSR row start
__device__ int   g_pos[N_NODES];                // fill cursor
__device__ int   g_esrc[N_EDGES];               // dst-sorted src indices

// ---------------------------------------------------------------------------
// 0) zero the degree histogram
// ---------------------------------------------------------------------------
__global__ void zero_cnt_kernel() {
    int i = blockIdx.x * blockDim.x + threadIdx.x;
    if (i < N_NODES) g_cnt[i] = 0;
}

// ---------------------------------------------------------------------------
// 1) histogram of dst (degree)
// ---------------------------------------------------------------------------
__global__ void hist_kernel(const int* __restrict__ dst) {
    int i = blockIdx.x * blockDim.x + threadIdx.x;
    if (i < N_EDGES) atomicAdd(&g_cnt[dst[i]], 1);
}

// ---------------------------------------------------------------------------
// 2) single-block exclusive scan of g_cnt -> g_start, g_pos
//    1024 threads, each owns a contiguous chunk of 49 elements.
// ---------------------------------------------------------------------------
#define SCAN_T 1024
#define SCAN_C 49   // ceil(50000/1024)

__global__ void __launch_bounds__(SCAN_T) scan_kernel() {
    __shared__ int part[SCAN_T];
    const int t = threadIdx.x;
    const int base = t * SCAN_C;

    int s = 0;
    #pragma unroll 7
    for (int i = 0; i < SCAN_C; i++) {
        int idx = base + i;
        if (idx < N_NODES) s += g_cnt[idx];
    }
    part[t] = s;
    __syncthreads();

    // Hillis-Steele inclusive scan over 1024 partials
    #pragma unroll
    for (int off = 1; off < SCAN_T; off <<= 1) {
        int v = (t >= off) ? part[t - off] : 0;
        __syncthreads();
        part[t] += v;
        __syncthreads();
    }
    int run = part[t] - s;   // exclusive prefix for this chunk

    #pragma unroll 7
    for (int i = 0; i < SCAN_C; i++) {
        int idx = base + i;
        if (idx < N_NODES) {
            g_start[idx] = run;
            g_pos[idx]   = run;
            run += g_cnt[idx];
        }
    }
}

// ---------------------------------------------------------------------------
// 3) fill dst-sorted edge list
// ---------------------------------------------------------------------------
__global__ void fill_kernel(const int* __restrict__ src,
                            const int* __restrict__ dst) {
    int i = blockIdx.x * blockDim.x + threadIdx.x;
    if (i < N_EDGES) {
        int slot = atomicAdd(&g_pos[dst[i]], 1);
        g_esrc[slot] = src[i];
    }
}

// ---------------------------------------------------------------------------
// 4) pull-aggregate: one warp per node, lane = one float4 column, MLP=4.
// ---------------------------------------------------------------------------
__global__ void __launch_bounds__(256) gather_kernel(const float4* __restrict__ x4)
{
    int node = (blockIdx.x * blockDim.x + threadIdx.x) >> 5;
    int lane = threadIdx.x & 31;
    if (node >= N_NODES) return;

    int start = g_start[node];
    int deg   = g_cnt[node];
    int end   = start + deg;

    float4 acc = make_float4(0.f, 0.f, 0.f, 0.f);
    int e = start;
    for (; e + 4 <= end; e += 4) {
        int i0 = __ldg(&g_esrc[e]);
        int i1 = __ldg(&g_esrc[e + 1]);
        int i2 = __ldg(&g_esrc[e + 2]);
        int i3 = __ldg(&g_esrc[e + 3]);
        float4 v0 = x4[(size_t)i0 * (D / 4) + lane];
        float4 v1 = x4[(size_t)i1 * (D / 4) + lane];
        float4 v2 = x4[(size_t)i2 * (D / 4) + lane];
        float4 v3 = x4[(size_t)i3 * (D / 4) + lane];
        acc.x += (v0.x + v1.x) + (v2.x + v3.x);
        acc.y += (v0.y + v1.y) + (v2.y + v3.y);
        acc.z += (v0.z + v1.z) + (v2.z + v3.z);
        acc.w += (v0.w + v1.w) + (v2.w + v3.w);
    }
    for (; e < end; e++) {
        int i0 = __ldg(&g_esrc[e]);
        float4 v0 = x4[(size_t)i0 * (D / 4) + lane];
        acc.x += v0.x; acc.y += v0.y; acc.z += v0.z; acc.w += v0.w;
    }

    float rdeg = 1.0f / fmaxf((float)deg, 1.0f);
    acc.x *= rdeg; acc.y *= rdeg; acc.z *= rdeg; acc.w *= rdeg;
    reinterpret_cast<float4*>(g_mean)[(size_t)node * (D / 4) + lane] = acc;
}

// ---------------------------------------------------------------------------
// 5) fused GEMM + epilogue:  out = x + relu( g_mean @ W_l + x @ W_r + b )
//    A[50000 x 256] = [mean | x], B[256 x 128] = [W_l ; W_r]
//    128-row tile, 256 threads, 8x8 micro-tile, packed fp32x2 FMA,
//    B pairs loaded straight as ld.shared.b64.
// ---------------------------------------------------------------------------
#define BM 128
#define KC 32
#define KTOT 256

union F2U { float2 f; unsigned long long u; };

__device__ __forceinline__ unsigned long long splat2(float v) {
    unsigned long long r;
    asm("mov.b64 %0, {%1, %1};" : "=l"(r) : "f"(v));
    return r;
}
__device__ __forceinline__ void fma2(unsigned long long& acc,
                                     unsigned long long a,
                                     unsigned long long b) {
    asm("fma.rn.f32x2 %0, %1, %2, %0;" : "+l"(acc) : "l"(a), "l"(b));
}

__global__ void __launch_bounds__(256, 1) gemm_kernel(
    const float* __restrict__ x,
    const float* __restrict__ Wl,
    const float* __restrict__ bias,
    const float* __restrict__ Wr,
    float* __restrict__ out)
{
    extern __shared__ float smem[];
    float* Bs = smem;                     // KTOT * 128 floats (128 KB)
    float* As = smem + KTOT * 128;        // KC * 128 floats (16 KB), layout [k][m]
    float* bs = As + KC * 128;            // 128 floats

    const int tid = threadIdx.x;
    const int row0 = blockIdx.x * BM;

    // Stacked weights [W_l ; W_r] into Bs[k][n]
    {
        const float4* wl4 = reinterpret_cast<const float4*>(Wl);
        const float4* wr4 = reinterpret_cast<const float4*>(Wr);
        float4* Bs4 = reinterpret_cast<float4*>(Bs);
        #pragma unroll
        for (int i = 0; i < 16; i++)
            Bs4[tid + 256 * i] = wl4[tid + 256 * i];
        #pragma unroll
        for (int i = 0; i < 16; i++)
            Bs4[4096 + tid + 256 * i] = wr4[tid + 256 * i];
        if (tid < 128) bs[tid] = bias[tid];
    }

    const int tx = tid & 15;
    const int ty = tid >> 4;
    const int tx8 = tx * 8;
    const int ty8 = ty * 8;

    unsigned long long acc[8][4];
    #pragma unroll
    for (int i = 0; i < 8; i++)
        #pragma unroll
        for (int j = 0; j < 4; j++)
            acc[i][j] = 0ull;

    const int am  = tid & 127;
    const int akq = tid >> 7;            // 0 or 1
    int ar = row0 + am;
    if (ar >= N_NODES) ar = N_NODES - 1;
    const float4* mean4row = reinterpret_cast<const float4*>(g_mean + (size_t)ar * D);
    const float4* x4row    = reinterpret_cast<const float4*>(x + (size_t)ar * D);

    #pragma unroll 1
    for (int kt = 0; kt < KTOT / KC; kt++) {       // 8 iterations
        const int k0 = kt * KC;
        const bool is_mean = (k0 < 128);
        const float4* srow = is_mean ? mean4row : x4row;
        const int kb4 = (is_mean ? k0 : (k0 - 128)) >> 2;   // float4 base in row

        // Load & transpose A chunk: 256 threads cover 128 m x 8 float4-cols
        #pragma unroll
        for (int i = 0; i < 4; i++) {
            int kk4 = akq * 4 + i;       // 0..7
            float4 v = srow[kb4 + kk4];
            int kk = kk4 * 4;
            As[(kk + 0) * 128 + am] = v.x;
            As[(kk + 1) * 128 + am] = v.y;
            As[(kk + 2) * 128 + am] = v.z;
            As[(kk + 3) * 128 + am] = v.w;
        }
        __syncthreads();

        #pragma unroll
        for (int kk = 0; kk < KC; kk++) {
            const float4 a0 = *reinterpret_cast<const float4*>(&As[kk * 128 + ty8]);
            const float4 a1 = *reinterpret_cast<const float4*>(&As[kk * 128 + ty8 + 4]);
            const unsigned long long* Bp =
                reinterpret_cast<const unsigned long long*>(&Bs[(k0 + kk) * 128 + tx8]);
            unsigned long long bp0 = Bp[0];
            unsigned long long bp1 = Bp[1];
            unsigned long long bp2 = Bp[2];
            unsigned long long bp3 = Bp[3];

            float av[8] = {a0.x, a0.y, a0.z, a0.w, a1.x, a1.y, a1.z, a1.w};
            #pragma unroll
            for (int m = 0; m < 8; m++) {
                unsigned long long as_ = splat2(av[m]);
                fma2(acc[m][0], as_, bp0);
                fma2(acc[m][1], as_, bp1);
                fma2(acc[m][2], as_, bp2);
                fma2(acc[m][3], as_, bp3);
            }
        }
        __syncthreads();
    }

    const float4 ba = *reinterpret_cast<const float4*>(&bs[tx8]);
    const float4 bb = *reinterpret_cast<const float4*>(&bs[tx8 + 4]);
    #pragma unroll
    for (int m = 0; m < 8; m++) {
        int r = row0 + ty8 + m;
        if (r < N_NODES) {
            const float4* xr = reinterpret_cast<const float4*>(x + (size_t)r * D + tx8);
            float4* outr = reinterpret_cast<float4*>(out + (size_t)r * D + tx8);
            float4 xa = xr[0], xb = xr[1];
            F2U u; float4 o;
            u.u = acc[m][0];
            o.x = xa.x + fmaxf(u.f.x + ba.x, 0.f);
            o.y = xa.y + fmaxf(u.f.y + ba.y, 0.f);
            u.u = acc[m][1];
            o.z = xa.z + fmaxf(u.f.x + ba.z, 0.f);
            o.w = xa.w + fmaxf(u.f.y + ba.w, 0.f);
            outr[0] = o;
            u.u = acc[m][2];
            o.x = xb.x + fmaxf(u.f.x + bb.x, 0.f);
            o.y = xb.y + fmaxf(u.f.y + bb.y, 0.f);
            u.u = acc[m][3];
            o.z = xb.z + fmaxf(u.f.x + bb.z, 0.f);
            o.w = xb.w + fmaxf(u.f.y + bb.w, 0.f);
            outr[1] = o;
        }
    }
}

// ---------------------------------------------------------------------------
// Exactly 6 launches per call so ncu (-s 5 -c 1) captures the GEMM.
// ---------------------------------------------------------------------------
extern "C" void kernel_launch(void* const* d_in, const int* in_sizes, int n_in,
                              void* d_out, int out_size)
{
    const float* x  = (const float*)d_in[0];
    const int*   ei = (const int*)d_in[1];      // [2, E]: src = ei[0:E], dst = ei[E:2E]
    const float* Wl = (const float*)d_in[2];
    const float* bl = (const float*)d_in[3];
    const float* Wr = (const float*)d_in[4];
    float* out = (float*)d_out;

    const int* src = ei;
    const int* dst = ei + N_EDGES;

    zero_cnt_kernel<<<(N_NODES + 255) / 256, 256>>>();                 // 0
    hist_kernel<<<(N_EDGES + 255) / 256, 256>>>(dst);                  // 1
    scan_kernel<<<1, SCAN_T>>>();                                      // 2
    fill_kernel<<<(N_EDGES + 255) / 256, 256>>>(src, dst);             // 3

    {
        long long threads = (long long)N_NODES * 32;
        int blocks = (int)((threads + 255) / 256);
        gather_kernel<<<blocks, 256>>>(reinterpret_cast<const float4*>(x));  // 4
    }

    {
        const int smem_bytes = (KTOT * 128 + KC * 128 + 128) * sizeof(float);
        cudaFuncSetAttribute(gemm_kernel,
                             cudaFuncAttributeMaxDynamicSharedMemorySize,
                             smem_bytes);
        int grid = (N_NODES + BM - 1) / BM;
        gemm_kernel<<<grid, 256, smem_bytes>>>(x, Wl, bl, Wr, out);    // 5
    }
}